// round 2
// baseline (speedup 1.0000x reference)
#include <cuda_runtime.h>
#include <cuda_bf16.h>
#include <math.h>

#define TPB 128

__global__ void eq_zero_kernel(float* __restrict__ p, int n){
  int i = blockIdx.x * blockDim.x + threadIdx.x;
  if (i < n) p[i] = 0.0f;
}

__device__ __forceinline__ void comp_h(const float B[10], const float* __restrict__ w1, float hr[64]){
  #pragma unroll
  for (int j = 0; j < 64; j += 4){
    float a0=0.f,a1=0.f,a2=0.f,a3=0.f;
    #pragma unroll
    for (int i = 0; i < 10; i++){
      float4 wv = *(const float4*)(w1 + i*64 + j);
      a0 = fmaf(B[i], wv.x, a0);
      a1 = fmaf(B[i], wv.y, a1);
      a2 = fmaf(B[i], wv.z, a2);
      a3 = fmaf(B[i], wv.w, a3);
    }
    hr[j+0] = fmaxf(a0, 0.f);
    hr[j+1] = fmaxf(a1, 0.f);
    hr[j+2] = fmaxf(a2, 0.f);
    hr[j+3] = fmaxf(a3, 0.f);
  }
}

template<int LD, int NQ>
__device__ __forceinline__ void wchunk(const float hr[64], const float* __restrict__ w2, int c0, float* dst){
  #pragma unroll
  for (int q = 0; q < NQ; q++){
    float a0=0.f,a1=0.f,a2=0.f,a3=0.f;
    #pragma unroll
    for (int j = 0; j < 64; j++){
      float4 wv = *(const float4*)(w2 + j*LD + c0 + 4*q);
      a0 = fmaf(hr[j], wv.x, a0);
      a1 = fmaf(hr[j], wv.y, a1);
      a2 = fmaf(hr[j], wv.z, a2);
      a3 = fmaf(hr[j], wv.w, a3);
    }
    dst[4*q+0]=a0; dst[4*q+1]=a1; dst[4*q+2]=a2; dst[4*q+3]=a3;
  }
}

__global__ __launch_bounds__(TPB) void eq_edge_kernel(
    const float* __restrict__ f_in,
    const int*   __restrict__ ei,
    const float* __restrict__ pos,
    const float* __restrict__ W1s, const float* __restrict__ W2s,
    const float* __restrict__ W1p, const float* __restrict__ W2p,
    const float* __restrict__ W1d, const float* __restrict__ W2d,
    float* __restrict__ fout,
    int E, float gscale)
{
  __shared__ __align__(16) float sW1[3][10][64];
  __shared__ __align__(16) float sW2s[64][12];
  __shared__ __align__(16) float sW2p[64][48];
  __shared__ __align__(16) float sW2d[64][80];

  for (int i = threadIdx.x; i < 640; i += TPB){
    ((float*)sW1)[i]        = W1s[i];
    ((float*)sW1)[640 + i]  = W1p[i];
    ((float*)sW1)[1280 + i] = W1d[i];
  }
  for (int i = threadIdx.x; i < 64*12; i += TPB)
    ((float*)sW2s)[i] = W2s[i] * gscale;          // all scalar-path eff factors = 1
  {
    const float ep[4] = {0.4082482904638631f,     // sqrt(1/2)/sqrt(3)
                         0.3333333333333333f,     // sqrt(1/3)/sqrt(3)
                         1.2909944487358056f,     // sqrt(5/3)
                         0.7071067811865476f};    // sqrt(1/2)
    for (int i = threadIdx.x; i < 64*48; i += TPB)
      ((float*)sW2p)[i] = W2p[i] * (gscale * ep[(i % 48) / 12]);
    const float ed[4] = {0.31622776601683794f,    // sqrt(1/2)/sqrt(5)
                         0.7745966692414834f,     // sqrt(3/5)
                         0.2f,                    // sqrt(1/5)/sqrt(5)
                         0.7071067811865476f};    // sqrt(1/2)
    for (int i = threadIdx.x; i < 64*80; i += TPB)
      ((float*)sW2d)[i] = W2d[i] * (gscale * ed[(i % 80) / 20]);
  }
  __syncthreads();

  int e = blockIdx.x * TPB + threadIdx.x;
  if (e >= E) return;

  const int row = ei[e];
  const int col = ei[E + e];

  const float dxv = pos[3*row+0] - pos[3*col+0];
  const float dyv = pos[3*row+1] - pos[3*col+1];
  const float dzv = pos[3*row+2] - pos[3*col+2];
  float r2   = dxv*dxv + dyv*dyv + dzv*dzv + 1e-12f;
  float rinv = rsqrtf(r2);
  float r    = r2 * rinv;
  if (!(r < 5.0f)) return;        // all radial basis bumps vanish
  const float ux = dxv*rinv, uy = dyv*rinv, uz = dzv*rinv;

  // spherical harmonics in reference order
  float t0 = 1.7320508075688772f * ux;
  float t1 = 1.7320508075688772f * uy;
  float t2 = 1.7320508075688772f * uz;
  float s0 = 3.872983346207417f * ux * uz;
  float s1 = 3.872983346207417f * ux * uy;
  float s2 = 1.1180339887498949f * (2.f*uy*uy - ux*ux - uz*uz);
  float s3 = 3.872983346207417f * uy * uz;
  float s4 = 1.9364916731037085f * (uz*uz - ux*ux);

  // soft-one-hot radial basis; sqrt(10) emb factor cancels W1/sqrt(10)
  float B[10];
  #pragma unroll
  for (int i = 0; i < 10; i++){
    float d  = r * 2.2f - (float)(i+1);
    float u1 = d + 1.0f;
    float u2 = 1.0f - d;
    B[i] = (u1 > 0.f && u2 > 0.f) ? 8.4335731f * __expf(-1.0f/u1 - 1.0f/u2) : 0.f;
  }

  // gather node features at 'row', summed over trailing size-2 axis
  const float2* fr = (const float2*)(f_in + (size_t)row * 162);
  const float xs = fr[0].x + fr[0].y;
  float xp[9];
  #pragma unroll
  for (int a = 0; a < 3; a++)
    #pragma unroll
    for (int b = 0; b < 3; b++){
      float2 v = fr[(1+a)*9 + (1+b)];
      xp[a*3+b] = v.x + v.y;
    }
  float xd[25];
  #pragma unroll
  for (int a = 0; a < 5; a++)
    #pragma unroll
    for (int b = 0; b < 5; b++){
      float2 v = fr[(4+a)*9 + (4+b)];
      xd[a*5+b] = v.x + v.y;
    }

  float* ob = fout + (size_t)col * 108;
  float hr[64];

  const float CA = 0.31622776601683794f;  // sqrt(1/10)
  const float CB = 0.18257418583505536f;  // sqrt(1/30)
  const float CG = 0.11952286093343936f;  // 1/sqrt(70)
  const float CH = 0.20701966780270626f;  // sqrt(3/70)

  // ---------------- scalar (l1=0) ----------------
  comp_h(B, (const float*)sW1[0], hr);
  {
    float w_[12];
    wchunk<12,3>(hr, (const float*)sW2s, 0, w_);
    #pragma unroll
    for (int w = 0; w < 4; w++) atomicAdd(ob + w, xs * w_[w]);
    float xt0 = xs*t0, xt1 = xs*t1, xt2 = xs*t2;
    #pragma unroll
    for (int w = 0; w < 4; w++){
      atomicAdd(ob + 4 + w*3 + 0, xt0 * w_[4+w]);
      atomicAdd(ob + 4 + w*3 + 1, xt1 * w_[4+w]);
      atomicAdd(ob + 4 + w*3 + 2, xt2 * w_[4+w]);
    }
    float xv[5] = {xs*s0, xs*s1, xs*s2, xs*s3, xs*s4};
    #pragma unroll
    for (int w = 0; w < 4; w++)
      #pragma unroll
      for (int k = 0; k < 5; k++) atomicAdd(ob + 16 + w*5 + k, xv[k] * w_[8+w]);
  }

  // ---------------- vector (l1=1) ----------------
  comp_h(B, (const float*)sW1[1], hr);
  {
    // ins1: l2=1 -> lo=0, cols 12..23
    float w_[12];
    wchunk<48,3>(hr, (const float*)sW2p, 12, w_);
    float a0=0.f,a1=0.f,a2=0.f,a3=0.f;
    #pragma unroll
    for (int u = 0; u < 3; u++){
      float y = xp[u*3]*t0 + xp[u*3+1]*t1 + xp[u*3+2]*t2;
      a0=fmaf(y,w_[u*4+0],a0); a1=fmaf(y,w_[u*4+1],a1);
      a2=fmaf(y,w_[u*4+2],a2); a3=fmaf(y,w_[u*4+3],a3);
    }
    atomicAdd(ob+36+0,a0); atomicAdd(ob+36+1,a1);
    atomicAdd(ob+36+2,a2); atomicAdd(ob+36+3,a3);
  }
  {
    // ins2: l2=1 -> lo=2, cols 24..35 (C112)
    float w_[12];
    wchunk<48,3>(hr, (const float*)sW2p, 24, w_);
    float acc[20];
    #pragma unroll
    for (int i = 0; i < 20; i++) acc[i] = 0.f;
    #pragma unroll
    for (int u = 0; u < 3; u++){
      float x0=xp[u*3], x1=xp[u*3+1], x2=xp[u*3+2];
      float y0 = CA*(x0*t2 + x2*t0);
      float y1 = CA*(x0*t1 + x1*t0);
      float y2 = CB*(2.f*x1*t1 - x0*t0 - x2*t2);
      float y3 = CA*(x1*t2 + x2*t1);
      float y4 = CA*(x2*t2 - x0*t0);
      #pragma unroll
      for (int w = 0; w < 4; w++){
        float ww = w_[u*4+w];
        acc[w*5+0]=fmaf(y0,ww,acc[w*5+0]); acc[w*5+1]=fmaf(y1,ww,acc[w*5+1]);
        acc[w*5+2]=fmaf(y2,ww,acc[w*5+2]); acc[w*5+3]=fmaf(y3,ww,acc[w*5+3]);
        acc[w*5+4]=fmaf(y4,ww,acc[w*5+4]);
      }
    }
    #pragma unroll
    for (int w = 0; w < 4; w++)
      #pragma unroll
      for (int k = 0; k < 5; k++) atomicAdd(ob + 52 + w*5 + k, acc[w*5+k]);
  }
  {
    // ins0 (cols 0..11) + ins3 (cols 36..47), both -> lo=1
    float acc[12];
    #pragma unroll
    for (int i = 0; i < 12; i++) acc[i] = 0.f;
    float w_[12];
    wchunk<48,3>(hr, (const float*)sW2p, 0, w_);
    #pragma unroll
    for (int u = 0; u < 3; u++)
      #pragma unroll
      for (int w = 0; w < 4; w++){
        float ww = w_[u*4+w];
        acc[w*3+0]=fmaf(xp[u*3+0],ww,acc[w*3+0]);
        acc[w*3+1]=fmaf(xp[u*3+1],ww,acc[w*3+1]);
        acc[w*3+2]=fmaf(xp[u*3+2],ww,acc[w*3+2]);
      }
    wchunk<48,3>(hr, (const float*)sW2p, 36, w_);
    // N[i][k] = sum_j s_j * C121[i][j][k],  C121[i][j][k] = C112[i][k][j]
    float N00 = -CB*s2 - CA*s4;
    float N01 =  CA*s1;
    float N02 =  CA*s0;
    float N11 =  2.f*CB*s2;
    float N12 =  CA*s3;
    float N22 = -CB*s2 + CA*s4;
    #pragma unroll
    for (int u = 0; u < 3; u++){
      float x0=xp[u*3], x1=xp[u*3+1], x2=xp[u*3+2];
      float y0 = x0*N00 + x1*N01 + x2*N02;
      float y1 = x0*N01 + x1*N11 + x2*N12;
      float y2 = x0*N02 + x1*N12 + x2*N22;
      #pragma unroll
      for (int w = 0; w < 4; w++){
        float ww = w_[u*4+w];
        acc[w*3+0]=fmaf(y0,ww,acc[w*3+0]);
        acc[w*3+1]=fmaf(y1,ww,acc[w*3+1]);
        acc[w*3+2]=fmaf(y2,ww,acc[w*3+2]);
      }
    }
    #pragma unroll
    for (int w = 0; w < 4; w++)
      #pragma unroll
      for (int k = 0; k < 3; k++) atomicAdd(ob + 40 + w*3 + k, acc[w*3+k]);
  }

  // ---------------- tensor (l1=2) ----------------
  comp_h(B, (const float*)sW1[2], hr);
  {
    // ins1: l2=1 -> lo=1, cols 20..39 (C211[i][j][k] = C112[j][k][i])
    float w_[20];
    wchunk<80,5>(hr, (const float*)sW2d, 20, w_);
    float acc[12];
    #pragma unroll
    for (int i = 0; i < 12; i++) acc[i] = 0.f;
    #pragma unroll
    for (int u = 0; u < 5; u++){
      float x0=xd[u*5], x1=xd[u*5+1], x2=xd[u*5+2], x3=xd[u*5+3], x4=xd[u*5+4];
      float y0 = CA*(x0*t2 + x1*t1 - x4*t0) - CB*x2*t0;
      float y1 = CA*(x1*t0 + x3*t2) + 2.f*CB*x2*t1;
      float y2 = CA*(x0*t0 + x3*t1 + x4*t2) - CB*x2*t2;
      #pragma unroll
      for (int w = 0; w < 4; w++){
        float ww = w_[u*4+w];
        acc[w*3+0]=fmaf(y0,ww,acc[w*3+0]);
        acc[w*3+1]=fmaf(y1,ww,acc[w*3+1]);
        acc[w*3+2]=fmaf(y2,ww,acc[w*3+2]);
      }
    }
    #pragma unroll
    for (int w = 0; w < 4; w++)
      #pragma unroll
      for (int k = 0; k < 3; k++) atomicAdd(ob + 76 + w*3 + k, acc[w*3+k]);
  }
  {
    // ins2: l2=2 -> lo=0, cols 40..59
    float w_[20];
    wchunk<80,5>(hr, (const float*)sW2d, 40, w_);
    float a0=0.f,a1=0.f,a2=0.f,a3=0.f;
    #pragma unroll
    for (int u = 0; u < 5; u++){
      float y = xd[u*5]*s0 + xd[u*5+1]*s1 + xd[u*5+2]*s2 + xd[u*5+3]*s3 + xd[u*5+4]*s4;
      a0=fmaf(y,w_[u*4+0],a0); a1=fmaf(y,w_[u*4+1],a1);
      a2=fmaf(y,w_[u*4+2],a2); a3=fmaf(y,w_[u*4+3],a3);
    }
    atomicAdd(ob+72+0,a0); atomicAdd(ob+72+1,a1);
    atomicAdd(ob+72+2,a2); atomicAdd(ob+72+3,a3);
  }
  {
    // ins0 (cols 0..19) + ins3 (cols 60..79), both -> lo=2
    float acc[20];
    #pragma unroll
    for (int i = 0; i < 20; i++) acc[i] = 0.f;
    float w_[20];
    wchunk<80,5>(hr, (const float*)sW2d, 0, w_);
    #pragma unroll
    for (int u = 0; u < 5; u++)
      #pragma unroll
      for (int w = 0; w < 4; w++){
        float ww = w_[u*4+w];
        #pragma unroll
        for (int k = 0; k < 5; k++)
          acc[w*5+k] = fmaf(xd[u*5+k], ww, acc[w*5+k]);
      }
    wchunk<80,5>(hr, (const float*)sW2d, 60, w_);
    // H[i][k] = sum_j s_j * C222[i][j][k]  (C222 sign-canonicalized: global flip)
    float h00 = 2.f*CG*s2;
    float h01 = -CH*s3;
    float h02 = 2.f*CG*s0;
    float h03 = -CH*s1;
    float h11 = -CG*s2 + CH*s4;
    float h12 = -CG*s1;
    float h13 = -CH*s0;
    float h14 =  CH*s1;
    float h22 = -2.f*CG*s2;
    float h23 = -CG*s3;
    float h24 = 2.f*CG*s4;
    float h33 = -CG*s2 - CH*s4;
    float h34 = -CH*s3;
    float h44 = 2.f*CG*s2;
    #pragma unroll
    for (int u = 0; u < 5; u++){
      float x0=xd[u*5], x1=xd[u*5+1], x2=xd[u*5+2], x3=xd[u*5+3], x4=xd[u*5+4];
      float y0 = x0*h00 + x1*h01 + x2*h02 + x3*h03;
      float y1 = x0*h01 + x1*h11 + x2*h12 + x3*h13 + x4*h14;
      float y2 = x0*h02 + x1*h12 + x2*h22 + x3*h23 + x4*h24;
      float y3 = x0*h03 + x1*h13 + x2*h23 + x3*h33 + x4*h34;
      float y4 =          x1*h14 + x2*h24 + x3*h34 + x4*h44;
      #pragma unroll
      for (int w = 0; w < 4; w++){
        float ww = w_[u*4+w];
        acc[w*5+0]=fmaf(y0,ww,acc[w*5+0]); acc[w*5+1]=fmaf(y1,ww,acc[w*5+1]);
        acc[w*5+2]=fmaf(y2,ww,acc[w*5+2]); acc[w*5+3]=fmaf(y3,ww,acc[w*5+3]);
        acc[w*5+4]=fmaf(y4,ww,acc[w*5+4]);
      }
    }
    #pragma unroll
    for (int w = 0; w < 4; w++)
      #pragma unroll
      for (int k = 0; k < 5; k++) atomicAdd(ob + 88 + w*5 + k, acc[w*5+k]);
  }
}

extern "C" void kernel_launch(void* const* d_in, const int* in_sizes, int n_in,
                              void* d_out, int out_size) {
  const float* f_in = (const float*)d_in[0];
  const int*   ei   = (const int*)d_in[1];
  const float* pos  = (const float*)d_in[2];
  const float* W1s  = (const float*)d_in[5];
  const float* W2s  = (const float*)d_in[6];
  const float* W1p  = (const float*)d_in[7];
  const float* W2p  = (const float*)d_in[8];
  const float* W1d  = (const float*)d_in[9];
  const float* W2d  = (const float*)d_in[10];
  float* fout = (float*)d_out;

  int E = in_sizes[1] / 2;

  // gscale = (sqrt(2)/8 from FC) * (1/sqrt(16) neighbor norm)
  float gscale = 0.04419417382415922f;

  eq_zero_kernel<<<(out_size + 255) / 256, 256>>>(fout, out_size);
  eq_edge_kernel<<<(E + TPB - 1) / TPB, TPB>>>(
      f_in, ei, pos, W1s, W2s, W1p, W2p, W1d, W2d, fout, E, gscale);
}

// round 3
// speedup vs baseline: 4.3070x; 4.3070x over previous
#include <cuda_runtime.h>
#include <cuda_bf16.h>
#include <math.h>

#define TPB 128
#define NB 8192          // radial table bins over [0,5)
#define TROW 144         // padded table row (floats)
#define XROW 36          // padded per-node sum row (floats)
#define MAXN 50000

__device__ float g_wtab[NB * TROW];
__device__ float g_xsum[MAXN * XROW];

__global__ void eq_zero_kernel(float* __restrict__ p, int n){
  int i = blockIdx.x * blockDim.x + threadIdx.x;
  if (i < n) p[i] = 0.0f;
}

// ---------- per-node feature sums: xs, xp[9], xd[25] ----------
__global__ void nodesum_kernel(const float* __restrict__ f_in, int n_nodes){
  int v = blockIdx.x * blockDim.x + threadIdx.x;
  if (v >= n_nodes) return;
  const float2* fr = (const float2*)(f_in + (size_t)v * 162);
  float* o = g_xsum + (size_t)v * XROW;
  #pragma unroll
  for (int a = 0; a < 5; a++)
    #pragma unroll
    for (int b = 0; b < 5; b++){
      float2 t = fr[(4+a)*9 + (4+b)];
      o[a*5+b] = t.x + t.y;                       // xd at [0..24]
    }
  #pragma unroll
  for (int a = 0; a < 3; a++)
    #pragma unroll
    for (int b = 0; b < 3; b++){
      float2 t = fr[(1+a)*9 + (1+b)];
      o[25 + a*3+b] = t.x + t.y;                  // xp at [25..33]
    }
  float2 t0 = fr[0];
  o[34] = t0.x + t0.y;                            // xs at [34]
  o[35] = 0.f;
}

// ---------- radial weight table: w(r) in R^140, all constants folded ----------
__global__ void tab_kernel(const float* __restrict__ W1s, const float* __restrict__ W2s,
                           const float* __restrict__ W1p, const float* __restrict__ W2p,
                           const float* __restrict__ W1d, const float* __restrict__ W2d,
                           float gscale){
  __shared__ float sh[192];
  const int bin = blockIdx.x;
  const int tid = threadIdx.x;
  const float r = (float)bin * (5.0f / (float)NB);

  float B[10];
  #pragma unroll
  for (int i = 0; i < 10; i++){
    float d  = r * 2.2f - (float)(i+1);
    float u1 = d + 1.0f;
    float u2 = 1.0f - d;
    B[i] = (u1 > 0.f && u2 > 0.f) ? 8.4335731f * __expf(-1.0f/u1 - 1.0f/u2) : 0.f;
  }
  // h = relu(B @ W1) for the 3 sections (64 each)
  {
    int sec = tid / 64, j = tid % 64;   // tid < 192 always (block=192)
    const float* W1 = (sec == 0) ? W1s : (sec == 1) ? W1p : W1d;
    float a = 0.f;
    #pragma unroll
    for (int i = 0; i < 10; i++) a = fmaf(B[i], W1[i*64 + j], a);
    sh[tid] = fmaxf(a, 0.f);
  }
  __syncthreads();

  if (tid < 140){
    const float ep[4] = {0.4082482904638631f, 0.3333333333333333f,
                         1.2909944487358056f, 0.7071067811865476f};
    const float ed[4] = {0.31622776601683794f, 0.7745966692414834f,
                         0.2f, 0.7071067811865476f};
    const float* h; const float* W2; int LD, c; float eff;
    if (tid < 12)      { h = sh;       W2 = W2s; LD = 12; c = tid;      eff = gscale; }
    else if (tid < 60) { h = sh + 64;  W2 = W2p; LD = 48; c = tid - 12; eff = gscale * ep[c/12]; }
    else               { h = sh + 128; W2 = W2d; LD = 80; c = tid - 60; eff = gscale * ed[c/20]; }
    float acc = 0.f;
    #pragma unroll
    for (int j = 0; j < 64; j++) acc = fmaf(h[j], W2[j*LD + c], acc);
    g_wtab[(size_t)bin * TROW + tid] = acc * eff;
  }
}

// ---------- helpers ----------
__device__ __forceinline__ void lerp4(const float* __restrict__ ta, const float* __restrict__ tb,
                                      int c, float f, float* dst){
  float4 a = *(const float4*)(ta + c);
  float4 b = *(const float4*)(tb + c);
  dst[0] = fmaf(b.x - a.x, f, a.x);
  dst[1] = fmaf(b.y - a.y, f, a.y);
  dst[2] = fmaf(b.z - a.z, f, a.z);
  dst[3] = fmaf(b.w - a.w, f, a.w);
}

__device__ __forceinline__ void red4(float* p, float a, float b, float c, float d){
  asm volatile("red.global.add.v4.f32 [%0], {%1, %2, %3, %4};"
               :: "l"(p), "f"(a), "f"(b), "f"(c), "f"(d) : "memory");
}

// ---------- edge kernel ----------
__global__ __launch_bounds__(TPB) void eq_edge_kernel(
    const int* __restrict__ ei,
    const float* __restrict__ pos,
    float* __restrict__ fout,
    int E)
{
  int e = blockIdx.x * TPB + threadIdx.x;
  if (e >= E) return;

  const int row = ei[e];
  const int col = ei[E + e];

  const float dxv = pos[3*row+0] - pos[3*col+0];
  const float dyv = pos[3*row+1] - pos[3*col+1];
  const float dzv = pos[3*row+2] - pos[3*col+2];
  float r2   = dxv*dxv + dyv*dyv + dzv*dzv + 1e-12f;
  float rinv = rsqrtf(r2);
  float r    = r2 * rinv;
  if (!(r < 5.0f)) return;                    // all radial bumps vanish
  const float ux = dxv*rinv, uy = dyv*rinv, uz = dzv*rinv;

  // spherical harmonics (reference order)
  float t0 = 1.7320508075688772f * ux;
  float t1 = 1.7320508075688772f * uy;
  float t2 = 1.7320508075688772f * uz;
  float s0 = 3.872983346207417f * ux * uz;
  float s1 = 3.872983346207417f * ux * uy;
  float s2 = 1.1180339887498949f * (2.f*uy*uy - ux*ux - uz*uz);
  float s3 = 3.872983346207417f * uy * uz;
  float s4 = 1.9364916731037085f * (uz*uz - ux*ux);

  // radial table lookup
  float fb = r * ((float)NB / 5.0f);
  int ib = (int)fb;
  if (ib > NB - 2) ib = NB - 2;
  float f = fb - (float)ib;
  const float* ta = g_wtab + (size_t)ib * TROW;
  const float* tb = ta + TROW;

  // node sums
  const float* xr = g_xsum + (size_t)row * XROW;
  float xd[25];
  #pragma unroll
  for (int i = 0; i < 24; i += 4){
    float4 q = *(const float4*)(xr + i);
    xd[i] = q.x; xd[i+1] = q.y; xd[i+2] = q.z; xd[i+3] = q.w;
  }
  xd[24] = xr[24];
  float xp[9];
  #pragma unroll
  for (int i = 0; i < 9; i++) xp[i] = xr[25 + i];
  const float xs = xr[34];

  float* ob = fout + (size_t)col * 108;

  const float CA = 0.31622776601683794f;  // sqrt(1/10)
  const float CB = 0.18257418583505536f;  // sqrt(1/30)
  const float CG = 0.11952286093343936f;  // 1/sqrt(70)
  const float CH = 0.20701966780270626f;  // sqrt(3/70)

  float w_[20];

  // ---------------- scalar (l1=0): table cols 0..11 ----------------
  lerp4(ta, tb, 0, f, w_); lerp4(ta, tb, 4, f, w_+4); lerp4(ta, tb, 8, f, w_+8);
  {
    red4(ob + 0, xs*w_[0], xs*w_[1], xs*w_[2], xs*w_[3]);
    float xt0 = xs*t0, xt1 = xs*t1, xt2 = xs*t2;
    red4(ob + 4,  xt0*w_[4], xt1*w_[4], xt2*w_[4], xt0*w_[5]);
    red4(ob + 8,  xt1*w_[5], xt2*w_[5], xt0*w_[6], xt1*w_[6]);
    red4(ob + 12, xt2*w_[6], xt0*w_[7], xt1*w_[7], xt2*w_[7]);
    float xv0 = xs*s0, xv1 = xs*s1, xv2 = xs*s2, xv3 = xs*s3, xv4 = xs*s4;
    red4(ob + 16, xv0*w_[8],  xv1*w_[8],  xv2*w_[8],  xv3*w_[8]);
    red4(ob + 20, xv4*w_[8],  xv0*w_[9],  xv1*w_[9],  xv2*w_[9]);
    red4(ob + 24, xv3*w_[9],  xv4*w_[9],  xv0*w_[10], xv1*w_[10]);
    red4(ob + 28, xv2*w_[10], xv3*w_[10], xv4*w_[10], xv0*w_[11]);
    red4(ob + 32, xv1*w_[11], xv2*w_[11], xv3*w_[11], xv4*w_[11]);
  }

  // ---------------- vector (l1=1) ----------------
  {
    // ins1: l2=1 -> lo=0 (table cols 24..35)
    lerp4(ta, tb, 24, f, w_); lerp4(ta, tb, 28, f, w_+4); lerp4(ta, tb, 32, f, w_+8);
    float a0=0.f,a1=0.f,a2=0.f,a3=0.f;
    #pragma unroll
    for (int u = 0; u < 3; u++){
      float y = xp[u*3]*t0 + xp[u*3+1]*t1 + xp[u*3+2]*t2;
      a0=fmaf(y,w_[u*4+0],a0); a1=fmaf(y,w_[u*4+1],a1);
      a2=fmaf(y,w_[u*4+2],a2); a3=fmaf(y,w_[u*4+3],a3);
    }
    red4(ob + 36, a0, a1, a2, a3);
  }
  {
    // ins2: l2=1 -> lo=2 (table cols 36..47)
    lerp4(ta, tb, 36, f, w_); lerp4(ta, tb, 40, f, w_+4); lerp4(ta, tb, 44, f, w_+8);
    float acc[20];
    #pragma unroll
    for (int i = 0; i < 20; i++) acc[i] = 0.f;
    #pragma unroll
    for (int u = 0; u < 3; u++){
      float x0=xp[u*3], x1=xp[u*3+1], x2=xp[u*3+2];
      float y0 = CA*(x0*t2 + x2*t0);
      float y1 = CA*(x0*t1 + x1*t0);
      float y2 = CB*(2.f*x1*t1 - x0*t0 - x2*t2);
      float y3 = CA*(x1*t2 + x2*t1);
      float y4 = CA*(x2*t2 - x0*t0);
      #pragma unroll
      for (int w = 0; w < 4; w++){
        float ww = w_[u*4+w];
        acc[w*5+0]=fmaf(y0,ww,acc[w*5+0]); acc[w*5+1]=fmaf(y1,ww,acc[w*5+1]);
        acc[w*5+2]=fmaf(y2,ww,acc[w*5+2]); acc[w*5+3]=fmaf(y3,ww,acc[w*5+3]);
        acc[w*5+4]=fmaf(y4,ww,acc[w*5+4]);
      }
    }
    red4(ob + 52, acc[0],  acc[1],  acc[2],  acc[3]);
    red4(ob + 56, acc[4],  acc[5],  acc[6],  acc[7]);
    red4(ob + 60, acc[8],  acc[9],  acc[10], acc[11]);
    red4(ob + 64, acc[12], acc[13], acc[14], acc[15]);
    red4(ob + 68, acc[16], acc[17], acc[18], acc[19]);
  }
  {
    // ins0 (table cols 12..23) + ins3 (table cols 48..59), both -> lo=1
    float acc[12];
    #pragma unroll
    for (int i = 0; i < 12; i++) acc[i] = 0.f;
    lerp4(ta, tb, 12, f, w_); lerp4(ta, tb, 16, f, w_+4); lerp4(ta, tb, 20, f, w_+8);
    #pragma unroll
    for (int u = 0; u < 3; u++)
      #pragma unroll
      for (int w = 0; w < 4; w++){
        float ww = w_[u*4+w];
        acc[w*3+0]=fmaf(xp[u*3+0],ww,acc[w*3+0]);
        acc[w*3+1]=fmaf(xp[u*3+1],ww,acc[w*3+1]);
        acc[w*3+2]=fmaf(xp[u*3+2],ww,acc[w*3+2]);
      }
    lerp4(ta, tb, 48, f, w_); lerp4(ta, tb, 52, f, w_+4); lerp4(ta, tb, 56, f, w_+8);
    float N00 = -CB*s2 - CA*s4;
    float N01 =  CA*s1;
    float N02 =  CA*s0;
    float N11 =  2.f*CB*s2;
    float N12 =  CA*s3;
    float N22 = -CB*s2 + CA*s4;
    #pragma unroll
    for (int u = 0; u < 3; u++){
      float x0=xp[u*3], x1=xp[u*3+1], x2=xp[u*3+2];
      float y0 = x0*N00 + x1*N01 + x2*N02;
      float y1 = x0*N01 + x1*N11 + x2*N12;
      float y2 = x0*N02 + x1*N12 + x2*N22;
      #pragma unroll
      for (int w = 0; w < 4; w++){
        float ww = w_[u*4+w];
        acc[w*3+0]=fmaf(y0,ww,acc[w*3+0]);
        acc[w*3+1]=fmaf(y1,ww,acc[w*3+1]);
        acc[w*3+2]=fmaf(y2,ww,acc[w*3+2]);
      }
    }
    red4(ob + 40, acc[0], acc[1], acc[2],  acc[3]);
    red4(ob + 44, acc[4], acc[5], acc[6],  acc[7]);
    red4(ob + 48, acc[8], acc[9], acc[10], acc[11]);
  }

  // ---------------- tensor (l1=2) ----------------
  {
    // ins2: l2=2 -> lo=0 (table cols 100..119)
    lerp4(ta, tb, 100, f, w_);   lerp4(ta, tb, 104, f, w_+4);
    lerp4(ta, tb, 108, f, w_+8); lerp4(ta, tb, 112, f, w_+12);
    lerp4(ta, tb, 116, f, w_+16);
    float a0=0.f,a1=0.f,a2=0.f,a3=0.f;
    #pragma unroll
    for (int u = 0; u < 5; u++){
      float y = xd[u*5]*s0 + xd[u*5+1]*s1 + xd[u*5+2]*s2 + xd[u*5+3]*s3 + xd[u*5+4]*s4;
      a0=fmaf(y,w_[u*4+0],a0); a1=fmaf(y,w_[u*4+1],a1);
      a2=fmaf(y,w_[u*4+2],a2); a3=fmaf(y,w_[u*4+3],a3);
    }
    red4(ob + 72, a0, a1, a2, a3);
  }
  {
    // ins1: l2=1 -> lo=1 (table cols 80..99)
    lerp4(ta, tb, 80, f, w_);   lerp4(ta, tb, 84, f, w_+4);
    lerp4(ta, tb, 88, f, w_+8); lerp4(ta, tb, 92, f, w_+12);
    lerp4(ta, tb, 96, f, w_+16);
    float acc[12];
    #pragma unroll
    for (int i = 0; i < 12; i++) acc[i] = 0.f;
    #pragma unroll
    for (int u = 0; u < 5; u++){
      float x0=xd[u*5], x1=xd[u*5+1], x2=xd[u*5+2], x3=xd[u*5+3], x4=xd[u*5+4];
      float y0 = CA*(x0*t2 + x1*t1 - x4*t0) - CB*x2*t0;
      float y1 = CA*(x1*t0 + x3*t2) + 2.f*CB*x2*t1;
      float y2 = CA*(x0*t0 + x3*t1 + x4*t2) - CB*x2*t2;
      #pragma unroll
      for (int w = 0; w < 4; w++){
        float ww = w_[u*4+w];
        acc[w*3+0]=fmaf(y0,ww,acc[w*3+0]);
        acc[w*3+1]=fmaf(y1,ww,acc[w*3+1]);
        acc[w*3+2]=fmaf(y2,ww,acc[w*3+2]);
      }
    }
    red4(ob + 76, acc[0], acc[1], acc[2],  acc[3]);
    red4(ob + 80, acc[4], acc[5], acc[6],  acc[7]);
    red4(ob + 84, acc[8], acc[9], acc[10], acc[11]);
  }
  {
    // ins0 (cols 60..79) + ins3 (cols 120..139), both -> lo=2
    float acc[20];
    #pragma unroll
    for (int i = 0; i < 20; i++) acc[i] = 0.f;
    lerp4(ta, tb, 60, f, w_);   lerp4(ta, tb, 64, f, w_+4);
    lerp4(ta, tb, 68, f, w_+8); lerp4(ta, tb, 72, f, w_+12);
    lerp4(ta, tb, 76, f, w_+16);
    #pragma unroll
    for (int u = 0; u < 5; u++)
      #pragma unroll
      for (int w = 0; w < 4; w++){
        float ww = w_[u*4+w];
        #pragma unroll
        for (int k = 0; k < 5; k++)
          acc[w*5+k] = fmaf(xd[u*5+k], ww, acc[w*5+k]);
      }
    lerp4(ta, tb, 120, f, w_);   lerp4(ta, tb, 124, f, w_+4);
    lerp4(ta, tb, 128, f, w_+8); lerp4(ta, tb, 132, f, w_+12);
    lerp4(ta, tb, 136, f, w_+16);
    float h00 = 2.f*CG*s2;
    float h01 = -CH*s3;
    float h02 = 2.f*CG*s0;
    float h03 = -CH*s1;
    float h11 = -CG*s2 + CH*s4;
    float h12 = -CG*s1;
    float h13 = -CH*s0;
    float h14 =  CH*s1;
    float h22 = -2.f*CG*s2;
    float h23 = -CG*s3;
    float h24 = 2.f*CG*s4;
    float h33 = -CG*s2 - CH*s4;
    float h34 = -CH*s3;
    float h44 = 2.f*CG*s2;
    #pragma unroll
    for (int u = 0; u < 5; u++){
      float x0=xd[u*5], x1=xd[u*5+1], x2=xd[u*5+2], x3=xd[u*5+3], x4=xd[u*5+4];
      float y0 = x0*h00 + x1*h01 + x2*h02 + x3*h03;
      float y1 = x0*h01 + x1*h11 + x2*h12 + x3*h13 + x4*h14;
      float y2 = x0*h02 + x1*h12 + x2*h22 + x3*h23 + x4*h24;
      float y3 = x0*h03 + x1*h13 + x2*h23 + x3*h33 + x4*h34;
      float y4 =          x1*h14 + x2*h24 + x3*h34 + x4*h44;
      #pragma unroll
      for (int w = 0; w < 4; w++){
        float ww = w_[u*4+w];
        acc[w*5+0]=fmaf(y0,ww,acc[w*5+0]); acc[w*5+1]=fmaf(y1,ww,acc[w*5+1]);
        acc[w*5+2]=fmaf(y2,ww,acc[w*5+2]); acc[w*5+3]=fmaf(y3,ww,acc[w*5+3]);
        acc[w*5+4]=fmaf(y4,ww,acc[w*5+4]);
      }
    }
    red4(ob + 88,  acc[0],  acc[1],  acc[2],  acc[3]);
    red4(ob + 92,  acc[4],  acc[5],  acc[6],  acc[7]);
    red4(ob + 96,  acc[8],  acc[9],  acc[10], acc[11]);
    red4(ob + 100, acc[12], acc[13], acc[14], acc[15]);
    red4(ob + 104, acc[16], acc[17], acc[18], acc[19]);
  }
}

extern "C" void kernel_launch(void* const* d_in, const int* in_sizes, int n_in,
                              void* d_out, int out_size) {
  const float* f_in = (const float*)d_in[0];
  const int*   ei   = (const int*)d_in[1];
  const float* pos  = (const float*)d_in[2];
  const float* W1s  = (const float*)d_in[5];
  const float* W2s  = (const float*)d_in[6];
  const float* W1p  = (const float*)d_in[7];
  const float* W2p  = (const float*)d_in[8];
  const float* W1d  = (const float*)d_in[9];
  const float* W2d  = (const float*)d_in[10];
  float* fout = (float*)d_out;

  int E = in_sizes[1] / 2;
  int n_nodes = in_sizes[0] / 162;

  // gscale = (sqrt(2)/8 from FC) * (1/sqrt(16) neighbor norm)
  float gscale = 0.04419417382415922f;

  tab_kernel<<<NB, 192>>>(W1s, W2s, W1p, W2p, W1d, W2d, gscale);
  nodesum_kernel<<<(n_nodes + 127) / 128, 128>>>(f_in, n_nodes);
  eq_zero_kernel<<<(out_size + 255) / 256, 256>>>(fout, out_size);
  eq_edge_kernel<<<(E + TPB - 1) / TPB, TPB>>>(ei, pos, fout, E);
}

// round 5
// speedup vs baseline: 5.2722x; 1.2241x over previous
#include <cuda_runtime.h>
#include <cuda_bf16.h>
#include <math.h>

#define TPB 128
#define NB 32768         // radial table bins over [0,5), nearest-bin sampled at centers
#define TROW 144         // padded table row (floats)
#define TBINS 128        // bins per table-build block
#define XROW 36          // padded per-node sum row (floats)
#define MAXN 50000

__device__ float g_wtab[NB * TROW];
__device__ float g_xsum[MAXN * XROW];
__device__ float4 g_pos4[MAXN];

__global__ void eq_zero_kernel(float* __restrict__ p, int n){
  int i = blockIdx.x * blockDim.x + threadIdx.x;
  if (i < n) p[i] = 0.0f;
}

// ---------- per-node: feature sums (xs, xp, xd) + packed pos ----------
__global__ void nodesum_kernel(const float* __restrict__ f_in,
                               const float* __restrict__ pos, int n_nodes){
  int v = blockIdx.x * blockDim.x + threadIdx.x;
  if (v >= n_nodes) return;
  const float2* fr = (const float2*)(f_in + (size_t)v * 162);
  float* o = g_xsum + (size_t)v * XROW;
  #pragma unroll
  for (int a = 0; a < 5; a++)
    #pragma unroll
    for (int b = 0; b < 5; b++){
      float2 t = fr[(4+a)*9 + (4+b)];
      o[a*5+b] = t.x + t.y;                       // xd at [0..24]
    }
  #pragma unroll
  for (int a = 0; a < 3; a++)
    #pragma unroll
    for (int b = 0; b < 3; b++){
      float2 t = fr[(1+a)*9 + (1+b)];
      o[25 + a*3+b] = t.x + t.y;                  // xp at [25..33]
    }
  float2 t0 = fr[0];
  o[34] = t0.x + t0.y;                            // xs at [34]
  o[35] = 0.f;
  g_pos4[v] = make_float4(pos[3*v+0], pos[3*v+1], pos[3*v+2], 0.f);
}

// ---------- radial weight table build: W cols in registers, h in shared ----------
__global__ __launch_bounds__(256) void tab_kernel(
    const float* __restrict__ W1s, const float* __restrict__ W2s,
    const float* __restrict__ W1p, const float* __restrict__ W2p,
    const float* __restrict__ W1d, const float* __restrict__ W2d,
    float gscale){
  __shared__ float sB[TBINS][10];
  __shared__ __align__(16) float sh[192];
  const int b0  = blockIdx.x * TBINS;
  const int tid = threadIdx.x;

  // phase 0: radial basis at all bin centers of this block
  for (int i = tid; i < TBINS*10; i += 256){
    int bb = i / 10, k = i % 10;
    float r  = ((float)(b0 + bb) + 0.5f) * (5.0f / (float)NB);
    float d  = r * 2.2f - (float)(k+1);
    float u1 = d + 1.0f;
    float u2 = 1.0f - d;
    sB[bb][k] = (u1 > 0.f && u2 > 0.f) ? 8.4335731f * __expf(-1.0f/u1 - 1.0f/u2) : 0.f;
  }

  // W1 column for threads 0..191 (s / p / d sections)
  float w1c[10];
  if (tid < 192){
    const float* W1 = (tid < 64) ? W1s : (tid < 128) ? W1p : W1d;
    int j = tid & 63;
    #pragma unroll
    for (int i = 0; i < 10; i++) w1c[i] = W1[i*64 + j];
  }
  // W2 column (with eff factor folded) for threads 0..139
  float w2c[64];
  int hoff = 0;
  if (tid < 140){
    const float ep[4] = {0.4082482904638631f, 0.3333333333333333f,
                         1.2909944487358056f, 0.7071067811865476f};
    const float ed[4] = {0.31622776601683794f, 0.7745966692414834f,
                         0.2f, 0.7071067811865476f};
    const float* W2; int LD, c; float eff;
    if (tid < 12)      { W2 = W2s; LD = 12; c = tid;      eff = gscale;            hoff = 0;   }
    else if (tid < 60) { W2 = W2p; LD = 48; c = tid - 12; eff = gscale * ep[c/12]; hoff = 64;  }
    else               { W2 = W2d; LD = 80; c = tid - 60; eff = gscale * ed[c/20]; hoff = 128; }
    #pragma unroll
    for (int j = 0; j < 64; j++) w2c[j] = W2[j*LD + c] * eff;
  }
  __syncthreads();

  for (int bb = 0; bb < TBINS; bb++){
    if (tid < 192){
      float a = 0.f;
      #pragma unroll
      for (int i = 0; i < 10; i++) a = fmaf(sB[bb][i], w1c[i], a);
      sh[tid] = fmaxf(a, 0.f);
    }
    __syncthreads();
    if (tid < 140){
      const float4* h4 = (const float4*)(sh + hoff);
      float acc = 0.f;
      #pragma unroll
      for (int q = 0; q < 16; q++){
        float4 hv = h4[q];
        acc = fmaf(hv.x, w2c[4*q+0], acc);
        acc = fmaf(hv.y, w2c[4*q+1], acc);
        acc = fmaf(hv.z, w2c[4*q+2], acc);
        acc = fmaf(hv.w, w2c[4*q+3], acc);
      }
      g_wtab[(size_t)(b0 + bb) * TROW + tid] = acc;
    }
    __syncthreads();
  }
}

// ---------- helpers ----------
__device__ __forceinline__ void ld4(const float* __restrict__ t, int c, float* dst){
  float4 q = *(const float4*)(t + c);
  dst[0]=q.x; dst[1]=q.y; dst[2]=q.z; dst[3]=q.w;
}

__device__ __forceinline__ void red4(float* p, float a, float b, float c, float d){
  asm volatile("red.global.add.v4.f32 [%0], {%1, %2, %3, %4};"
               :: "l"(p), "f"(a), "f"(b), "f"(c), "f"(d) : "memory");
}

// ---------- edge kernel ----------
__global__ __launch_bounds__(TPB) void eq_edge_kernel(
    const int* __restrict__ ei,
    float* __restrict__ fout,
    int E)
{
  int e = blockIdx.x * TPB + threadIdx.x;
  if (e >= E) return;

  const int row = ei[e];
  const int col = ei[E + e];

  float4 pr = g_pos4[row];
  float4 pc = g_pos4[col];
  const float dxv = pr.x - pc.x;
  const float dyv = pr.y - pc.y;
  const float dzv = pr.z - pc.z;
  float r2   = dxv*dxv + dyv*dyv + dzv*dzv + 1e-12f;
  float rinv = rsqrtf(r2);
  float r    = r2 * rinv;
  if (!(r < 5.0f)) return;                    // all radial bumps vanish
  const float ux = dxv*rinv, uy = dyv*rinv, uz = dzv*rinv;

  // spherical harmonics (reference order)
  float t0 = 1.7320508075688772f * ux;
  float t1 = 1.7320508075688772f * uy;
  float t2 = 1.7320508075688772f * uz;
  float s0 = 3.872983346207417f * ux * uz;
  float s1 = 3.872983346207417f * ux * uy;
  float s2 = 1.1180339887498949f * (2.f*uy*uy - ux*ux - uz*uz);
  float s3 = 3.872983346207417f * uy * uz;
  float s4 = 1.9364916731037085f * (uz*uz - ux*ux);

  // nearest-bin radial weights
  int ib = (int)(r * ((float)NB / 5.0f));
  if (ib > NB - 1) ib = NB - 1;
  const float* tw = g_wtab + (size_t)ib * TROW;

  // node sums
  const float* xr = g_xsum + (size_t)row * XROW;
  float xd[25];
  #pragma unroll
  for (int i = 0; i < 24; i += 4){
    float4 q = *(const float4*)(xr + i);
    xd[i] = q.x; xd[i+1] = q.y; xd[i+2] = q.z; xd[i+3] = q.w;
  }
  xd[24] = xr[24];
  float xp[9];
  #pragma unroll
  for (int i = 0; i < 9; i++) xp[i] = xr[25 + i];
  const float xs = xr[34];

  float* ob = fout + (size_t)col * 108;

  const float CA = 0.31622776601683794f;  // sqrt(1/10)
  const float CB = 0.18257418583505536f;  // sqrt(1/30)
  const float CG = 0.11952286093343936f;  // 1/sqrt(70)
  const float CH = 0.20701966780270626f;  // sqrt(3/70)

  float w_[20];

  // ---------------- scalar (l1=0): cols 0..11 ----------------
  ld4(tw, 0, w_); ld4(tw, 4, w_+4); ld4(tw, 8, w_+8);
  {
    red4(ob + 0, xs*w_[0], xs*w_[1], xs*w_[2], xs*w_[3]);
    float xt0 = xs*t0, xt1 = xs*t1, xt2 = xs*t2;
    red4(ob + 4,  xt0*w_[4], xt1*w_[4], xt2*w_[4], xt0*w_[5]);
    red4(ob + 8,  xt1*w_[5], xt2*w_[5], xt0*w_[6], xt1*w_[6]);
    red4(ob + 12, xt2*w_[6], xt0*w_[7], xt1*w_[7], xt2*w_[7]);
    float xv0 = xs*s0, xv1 = xs*s1, xv2 = xs*s2, xv3 = xs*s3, xv4 = xs*s4;
    red4(ob + 16, xv0*w_[8],  xv1*w_[8],  xv2*w_[8],  xv3*w_[8]);
    red4(ob + 20, xv4*w_[8],  xv0*w_[9],  xv1*w_[9],  xv2*w_[9]);
    red4(ob + 24, xv3*w_[9],  xv4*w_[9],  xv0*w_[10], xv1*w_[10]);
    red4(ob + 28, xv2*w_[10], xv3*w_[10], xv4*w_[10], xv0*w_[11]);
    red4(ob + 32, xv1*w_[11], xv2*w_[11], xv3*w_[11], xv4*w_[11]);
  }

  // ---------------- vector (l1=1) ----------------
  {
    // ins1: l2=1 -> lo=0 (cols 24..35)
    ld4(tw, 24, w_); ld4(tw, 28, w_+4); ld4(tw, 32, w_+8);
    float a0=0.f,a1=0.f,a2=0.f,a3=0.f;
    #pragma unroll
    for (int u = 0; u < 3; u++){
      float y = xp[u*3]*t0 + xp[u*3+1]*t1 + xp[u*3+2]*t2;
      a0=fmaf(y,w_[u*4+0],a0); a1=fmaf(y,w_[u*4+1],a1);
      a2=fmaf(y,w_[u*4+2],a2); a3=fmaf(y,w_[u*4+3],a3);
    }
    red4(ob + 36, a0, a1, a2, a3);
  }
  {
    // ins2: l2=1 -> lo=2 (cols 36..47)
    ld4(tw, 36, w_); ld4(tw, 40, w_+4); ld4(tw, 44, w_+8);
    float acc[20];
    #pragma unroll
    for (int i = 0; i < 20; i++) acc[i] = 0.f;
    #pragma unroll
    for (int u = 0; u < 3; u++){
      float x0=xp[u*3], x1=xp[u*3+1], x2=xp[u*3+2];
      float y0 = CA*(x0*t2 + x2*t0);
      float y1 = CA*(x0*t1 + x1*t0);
      float y2 = CB*(2.f*x1*t1 - x0*t0 - x2*t2);
      float y3 = CA*(x1*t2 + x2*t1);
      float y4 = CA*(x2*t2 - x0*t0);
      #pragma unroll
      for (int w = 0; w < 4; w++){
        float ww = w_[u*4+w];
        acc[w*5+0]=fmaf(y0,ww,acc[w*5+0]); acc[w*5+1]=fmaf(y1,ww,acc[w*5+1]);
        acc[w*5+2]=fmaf(y2,ww,acc[w*5+2]); acc[w*5+3]=fmaf(y3,ww,acc[w*5+3]);
        acc[w*5+4]=fmaf(y4,ww,acc[w*5+4]);
      }
    }
    red4(ob + 52, acc[0],  acc[1],  acc[2],  acc[3]);
    red4(ob + 56, acc[4],  acc[5],  acc[6],  acc[7]);
    red4(ob + 60, acc[8],  acc[9],  acc[10], acc[11]);
    red4(ob + 64, acc[12], acc[13], acc[14], acc[15]);
    red4(ob + 68, acc[16], acc[17], acc[18], acc[19]);
  }
  {
    // ins0 (cols 12..23) + ins3 (cols 48..59), both -> lo=1
    float acc[12];
    #pragma unroll
    for (int i = 0; i < 12; i++) acc[i] = 0.f;
    ld4(tw, 12, w_); ld4(tw, 16, w_+4); ld4(tw, 20, w_+8);
    #pragma unroll
    for (int u = 0; u < 3; u++)
      #pragma unroll
      for (int w = 0; w < 4; w++){
        float ww = w_[u*4+w];
        acc[w*3+0]=fmaf(xp[u*3+0],ww,acc[w*3+0]);
        acc[w*3+1]=fmaf(xp[u*3+1],ww,acc[w*3+1]);
        acc[w*3+2]=fmaf(xp[u*3+2],ww,acc[w*3+2]);
      }
    ld4(tw, 48, w_); ld4(tw, 52, w_+4); ld4(tw, 56, w_+8);
    float N00 = -CB*s2 - CA*s4;
    float N01 =  CA*s1;
    float N02 =  CA*s0;
    float N11 =  2.f*CB*s2;
    float N12 =  CA*s3;
    float N22 = -CB*s2 + CA*s4;
    #pragma unroll
    for (int u = 0; u < 3; u++){
      float x0=xp[u*3], x1=xp[u*3+1], x2=xp[u*3+2];
      float y0 = x0*N00 + x1*N01 + x2*N02;
      float y1 = x0*N01 + x1*N11 + x2*N12;
      float y2 = x0*N02 + x1*N12 + x2*N22;
      #pragma unroll
      for (int w = 0; w < 4; w++){
        float ww = w_[u*4+w];
        acc[w*3+0]=fmaf(y0,ww,acc[w*3+0]);
        acc[w*3+1]=fmaf(y1,ww,acc[w*3+1]);
        acc[w*3+2]=fmaf(y2,ww,acc[w*3+2]);
      }
    }
    red4(ob + 40, acc[0], acc[1], acc[2],  acc[3]);
    red4(ob + 44, acc[4], acc[5], acc[6],  acc[7]);
    red4(ob + 48, acc[8], acc[9], acc[10], acc[11]);
  }

  // ---------------- tensor (l1=2) ----------------
  {
    // ins2: l2=2 -> lo=0 (cols 100..119)
    ld4(tw, 100, w_);   ld4(tw, 104, w_+4);
    ld4(tw, 108, w_+8); ld4(tw, 112, w_+12);
    ld4(tw, 116, w_+16);
    float a0=0.f,a1=0.f,a2=0.f,a3=0.f;
    #pragma unroll
    for (int u = 0; u < 5; u++){
      float y = xd[u*5]*s0 + xd[u*5+1]*s1 + xd[u*5+2]*s2 + xd[u*5+3]*s3 + xd[u*5+4]*s4;
      a0=fmaf(y,w_[u*4+0],a0); a1=fmaf(y,w_[u*4+1],a1);
      a2=fmaf(y,w_[u*4+2],a2); a3=fmaf(y,w_[u*4+3],a3);
    }
    red4(ob + 72, a0, a1, a2, a3);
  }
  {
    // ins1: l2=1 -> lo=1 (cols 80..99)
    ld4(tw, 80, w_);   ld4(tw, 84, w_+4);
    ld4(tw, 88, w_+8); ld4(tw, 92, w_+12);
    ld4(tw, 96, w_+16);
    float acc[12];
    #pragma unroll
    for (int i = 0; i < 12; i++) acc[i] = 0.f;
    #pragma unroll
    for (int u = 0; u < 5; u++){
      float x0=xd[u*5], x1=xd[u*5+1], x2=xd[u*5+2], x3=xd[u*5+3], x4=xd[u*5+4];
      float y0 = CA*(x0*t2 + x1*t1 - x4*t0) - CB*x2*t0;
      float y1 = CA*(x1*t0 + x3*t2) + 2.f*CB*x2*t1;
      float y2 = CA*(x0*t0 + x3*t1 + x4*t2) - CB*x2*t2;
      #pragma unroll
      for (int w = 0; w < 4; w++){
        float ww = w_[u*4+w];
        acc[w*3+0]=fmaf(y0,ww,acc[w*3+0]);
        acc[w*3+1]=fmaf(y1,ww,acc[w*3+1]);
        acc[w*3+2]=fmaf(y2,ww,acc[w*3+2]);
      }
    }
    red4(ob + 76, acc[0], acc[1], acc[2],  acc[3]);
    red4(ob + 80, acc[4], acc[5], acc[6],  acc[7]);
    red4(ob + 84, acc[8], acc[9], acc[10], acc[11]);
  }
  {
    // ins0 (cols 60..79) + ins3 (cols 120..139), both -> lo=2
    float acc[20];
    #pragma unroll
    for (int i = 0; i < 20; i++) acc[i] = 0.f;
    ld4(tw, 60, w_);   ld4(tw, 64, w_+4);
    ld4(tw, 68, w_+8); ld4(tw, 72, w_+12);
    ld4(tw, 76, w_+16);
    #pragma unroll
    for (int u = 0; u < 5; u++)
      #pragma unroll
      for (int w = 0; w < 4; w++){
        float ww = w_[u*4+w];
        #pragma unroll
        for (int k = 0; k < 5; k++)
          acc[w*5+k] = fmaf(xd[u*5+k], ww, acc[w*5+k]);
      }
    ld4(tw, 120, w_);   ld4(tw, 124, w_+4);
    ld4(tw, 128, w_+8); ld4(tw, 132, w_+12);
    ld4(tw, 136, w_+16);
    float h00 = 2.f*CG*s2;
    float h01 = -CH*s3;
    float h02 = 2.f*CG*s0;
    float h03 = -CH*s1;
    float h11 = -CG*s2 + CH*s4;
    float h12 = -CG*s1;
    float h13 = -CH*s0;
    float h14 =  CH*s1;
    float h22 = -2.f*CG*s2;
    float h23 = -CG*s3;
    float h24 = 2.f*CG*s4;
    float h33 = -CG*s2 - CH*s4;
    float h34 = -CH*s3;
    float h44 = 2.f*CG*s2;
    #pragma unroll
    for (int u = 0; u < 5; u++){
      float x0=xd[u*5], x1=xd[u*5+1], x2=xd[u*5+2], x3=xd[u*5+3], x4=xd[u*5+4];
      float y0 = x0*h00 + x1*h01 + x2*h02 + x3*h03;
      float y1 = x0*h01 + x1*h11 + x2*h12 + x3*h13 + x4*h14;
      float y2 = x0*h02 + x1*h12 + x2*h22 + x3*h23 + x4*h24;
      float y3 = x0*h03 + x1*h13 + x2*h23 + x3*h33 + x4*h34;
      float y4 =          x1*h14 + x2*h24 + x3*h34 + x4*h44;
      #pragma unroll
      for (int w = 0; w < 4; w++){
        float ww = w_[u*4+w];
        acc[w*5+0]=fmaf(y0,ww,acc[w*5+0]); acc[w*5+1]=fmaf(y1,ww,acc[w*5+1]);
        acc[w*5+2]=fmaf(y2,ww,acc[w*5+2]); acc[w*5+3]=fmaf(y3,ww,acc[w*5+3]);
        acc[w*5+4]=fmaf(y4,ww,acc[w*5+4]);
      }
    }
    red4(ob + 88,  acc[0],  acc[1],  acc[2],  acc[3]);
    red4(ob + 92,  acc[4],  acc[5],  acc[6],  acc[7]);
    red4(ob + 96,  acc[8],  acc[9],  acc[10], acc[11]);
    red4(ob + 100, acc[12], acc[13], acc[14], acc[15]);
    red4(ob + 104, acc[16], acc[17], acc[18], acc[19]);
  }
}

extern "C" void kernel_launch(void* const* d_in, const int* in_sizes, int n_in,
                              void* d_out, int out_size) {
  const float* f_in = (const float*)d_in[0];
  const int*   ei   = (const int*)d_in[1];
  const float* pos  = (const float*)d_in[2];
  const float* W1s  = (const float*)d_in[5];
  const float* W2s  = (const float*)d_in[6];
  const float* W1p  = (const float*)d_in[7];
  const float* W2p  = (const float*)d_in[8];
  const float* W1d  = (const float*)d_in[9];
  const float* W2d  = (const float*)d_in[10];
  float* fout = (float*)d_out;

  int E = in_sizes[1] / 2;
  int n_nodes = in_sizes[0] / 162;

  // gscale = (sqrt(2)/8 from FC) * (1/sqrt(16) neighbor norm)
  float gscale = 0.04419417382415922f;

  tab_kernel<<<NB / TBINS, 256>>>(W1s, W2s, W1p, W2p, W1d, W2d, gscale);
  nodesum_kernel<<<(n_nodes + 127) / 128, 128>>>(f_in, pos, n_nodes);
  eq_zero_kernel<<<(out_size + 255) / 256, 256>>>(fout, out_size);
  eq_edge_kernel<<<(E + TPB - 1) / TPB, TPB>>>(ei, fout, E);
}

// round 7
// speedup vs baseline: 6.4481x; 1.2230x over previous
#include <cuda_runtime.h>
#include <cuda_bf16.h>
#include <cuda_fp16.h>
#include <math.h>

#define TPB 128
#define NB 32768         // radial table bins over [0,5), nearest-bin at centers
#define TROW 176         // padded table row (halfs), groups 16B-aligned
#define TBINS 64         // bins per table-build block
#define XROW 40          // per-node sum row (halfs)
#define MAXN 50000

__device__ __half g_wtab[NB * TROW];
__device__ __half g_xsum[MAXN * XROW];
__device__ float4 g_pos4[MAXN];

__global__ void eq_zero_kernel(float* __restrict__ p, int n){
  int i = blockIdx.x * blockDim.x + threadIdx.x;
  if (i < n) p[i] = 0.0f;
}

// column (0..139) -> padded half offset within a table row
__host__ __device__ __forceinline__ int colmap(int c){
  if (c < 12) return c;                                   // S
  if (c < 60){ int g = (c-12)/12; return 16 + 16*g + (c-12)%12; }  // P groups
  int g = (c-60)/20; return 80 + 24*g + (c-60)%20;        // D groups
}

// ---------- per-node: fp16 feature sums (xd, xp, xs) + packed pos ----------
__global__ void nodesum_kernel(const float* __restrict__ f_in,
                               const float* __restrict__ pos, int n_nodes){
  int v = blockIdx.x * blockDim.x + threadIdx.x;
  if (v >= n_nodes) return;
  const float2* fr = (const float2*)(f_in + (size_t)v * 162);
  __half tmp[XROW];
  #pragma unroll
  for (int a = 0; a < 5; a++)
    #pragma unroll
    for (int b = 0; b < 5; b++){
      float2 t = fr[(4+a)*9 + (4+b)];
      tmp[a*5+b] = __float2half_rn(t.x + t.y);            // xd at [0..24]
    }
  #pragma unroll
  for (int a = 0; a < 3; a++)
    #pragma unroll
    for (int b = 0; b < 3; b++){
      float2 t = fr[(1+a)*9 + (1+b)];
      tmp[25 + a*3+b] = __float2half_rn(t.x + t.y);       // xp at [25..33]
    }
  float2 t0 = fr[0];
  tmp[34] = __float2half_rn(t0.x + t0.y);                 // xs at [34]
  #pragma unroll
  for (int i = 35; i < XROW; i++) tmp[i] = __float2half_rn(0.f);
  uint4* dst = (uint4*)(g_xsum + (size_t)v * XROW);
  const uint4* src = (const uint4*)tmp;
  #pragma unroll
  for (int q = 0; q < 5; q++) dst[q] = src[q];
  g_pos4[v] = make_float4(pos[3*v+0], pos[3*v+1], pos[3*v+2], 0.f);
}

// ---------- radial weight table build ----------
__global__ __launch_bounds__(256) void tab_kernel(
    const float* __restrict__ W1s, const float* __restrict__ W2s,
    const float* __restrict__ W1p, const float* __restrict__ W2p,
    const float* __restrict__ W1d, const float* __restrict__ W2d,
    float gscale){
  __shared__ float sB[TBINS][10];
  __shared__ __align__(16) float sh[192];
  const int b0  = blockIdx.x * TBINS;
  const int tid = threadIdx.x;

  for (int i = tid; i < TBINS*10; i += 256){
    int bb = i / 10, k = i % 10;
    float r  = ((float)(b0 + bb) + 0.5f) * (5.0f / (float)NB);
    float d  = r * 2.2f - (float)(k+1);
    float u1 = d + 1.0f;
    float u2 = 1.0f - d;
    sB[bb][k] = (u1 > 0.f && u2 > 0.f) ? 8.4335731f * __expf(-1.0f/u1 - 1.0f/u2) : 0.f;
  }

  float w1c[10];
  if (tid < 192){
    const float* W1 = (tid < 64) ? W1s : (tid < 128) ? W1p : W1d;
    int j = tid & 63;
    #pragma unroll
    for (int i = 0; i < 10; i++) w1c[i] = W1[i*64 + j];
  }
  float w2c[64];
  int hoff = 0, dstoff = 0;
  if (tid < 140){
    const float ep[4] = {0.4082482904638631f, 0.3333333333333333f,
                         1.2909944487358056f, 0.7071067811865476f};
    const float ed[4] = {0.31622776601683794f, 0.7745966692414834f,
                         0.2f, 0.7071067811865476f};
    const float* W2; int LD, c; float eff;
    if (tid < 12)      { W2 = W2s; LD = 12; c = tid;      eff = gscale;            hoff = 0;   }
    else if (tid < 60) { W2 = W2p; LD = 48; c = tid - 12; eff = gscale * ep[c/12]; hoff = 64;  }
    else               { W2 = W2d; LD = 80; c = tid - 60; eff = gscale * ed[c/20]; hoff = 128; }
    #pragma unroll
    for (int j = 0; j < 64; j++) w2c[j] = W2[j*LD + c] * eff;
    dstoff = colmap(tid);
  }
  __syncthreads();

  for (int bb = 0; bb < TBINS; bb++){
    if (tid < 192){
      float a = 0.f;
      #pragma unroll
      for (int i = 0; i < 10; i++) a = fmaf(sB[bb][i], w1c[i], a);
      sh[tid] = fmaxf(a, 0.f);
    }
    __syncthreads();
    if (tid < 140){
      const float4* h4 = (const float4*)(sh + hoff);
      float acc = 0.f;
      #pragma unroll
      for (int q = 0; q < 16; q++){
        float4 hv = h4[q];
        acc = fmaf(hv.x, w2c[4*q+0], acc);
        acc = fmaf(hv.y, w2c[4*q+1], acc);
        acc = fmaf(hv.z, w2c[4*q+2], acc);
        acc = fmaf(hv.w, w2c[4*q+3], acc);
      }
      g_wtab[(size_t)(b0 + bb) * TROW + dstoff] = __float2half_rn(acc);
    }
    __syncthreads();
  }
}

// ---------- helpers ----------
__device__ __forceinline__ void unp2(unsigned u, float* w){
  __half2 h;
  *reinterpret_cast<unsigned*>(&h) = u;
  float2 f = __half22float2(h);
  w[0] = f.x; w[1] = f.y;
}

__device__ __forceinline__ void ldh12(const __half* __restrict__ t, float* w){
  uint4 a = *(const uint4*)(t);
  uint2 b = *(const uint2*)(t + 8);
  unp2(a.x, w);   unp2(a.y, w+2); unp2(a.z, w+4); unp2(a.w, w+6);
  unp2(b.x, w+8); unp2(b.y, w+10);
}

__device__ __forceinline__ void ldh20(const __half* __restrict__ t, float* w){
  uint4 a = *(const uint4*)(t);
  uint4 b = *(const uint4*)(t + 8);
  uint2 c = *(const uint2*)(t + 16);
  unp2(a.x, w);    unp2(a.y, w+2);  unp2(a.z, w+4);  unp2(a.w, w+6);
  unp2(b.x, w+8);  unp2(b.y, w+10); unp2(b.z, w+12); unp2(b.w, w+14);
  unp2(c.x, w+16); unp2(c.y, w+18);
}

__device__ __forceinline__ void red4(float* p, float a, float b, float c, float d){
  asm volatile("red.global.add.v4.f32 [%0], {%1, %2, %3, %4};"
               :: "l"(p), "f"(a), "f"(b), "f"(c), "f"(d) : "memory");
}

// ---------- edge kernel ----------
__global__ __launch_bounds__(TPB) void eq_edge_kernel(
    const int* __restrict__ ei,
    float* __restrict__ fout,
    int E)
{
  int e = blockIdx.x * TPB + threadIdx.x;
  if (e >= E) return;

  const int row = ei[e];
  const int col = ei[E + e];

  float4 pr = g_pos4[row];
  float4 pc = g_pos4[col];
  const float dxv = pr.x - pc.x;
  const float dyv = pr.y - pc.y;
  const float dzv = pr.z - pc.z;
  float r2   = dxv*dxv + dyv*dyv + dzv*dzv + 1e-12f;
  float rinv = rsqrtf(r2);
  float r    = r2 * rinv;
  if (!(r < 5.0f)) return;                    // all radial bumps vanish
  const float ux = dxv*rinv, uy = dyv*rinv, uz = dzv*rinv;

  // spherical harmonics (reference order)
  float t0 = 1.7320508075688772f * ux;
  float t1 = 1.7320508075688772f * uy;
  float t2 = 1.7320508075688772f * uz;
  float s0 = 3.872983346207417f * ux * uz;
  float s1 = 3.872983346207417f * ux * uy;
  float s2 = 1.1180339887498949f * (2.f*uy*uy - ux*ux - uz*uz);
  float s3 = 3.872983346207417f * uy * uz;
  float s4 = 1.9364916731037085f * (uz*uz - ux*ux);

  // nearest-bin radial weights
  int ib = (int)(r * ((float)NB / 5.0f));
  if (ib > NB - 1) ib = NB - 1;
  const __half* tw = g_wtab + (size_t)ib * TROW;

  // node sums (fp16 -> f32)
  float xf[40];
  {
    const uint4* xp4 = (const uint4*)(g_xsum + (size_t)row * XROW);
    #pragma unroll
    for (int q = 0; q < 5; q++){
      uint4 a = xp4[q];
      unp2(a.x, xf + 8*q);     unp2(a.y, xf + 8*q + 2);
      unp2(a.z, xf + 8*q + 4); unp2(a.w, xf + 8*q + 6);
    }
  }
  const float* xd = xf;          // [0..24]
  const float* xp = xf + 25;     // [25..33]
  const float xs  = xf[34];

  float* ob = fout + (size_t)col * 108;

  const float CA = 0.31622776601683794f;  // sqrt(1/10)
  const float CB = 0.18257418583505536f;  // sqrt(1/30)
  const float CG = 0.11952286093343936f;  // 1/sqrt(70)
  const float CH = 0.20701966780270626f;  // sqrt(3/70)

  float w_[20];

  // ---------------- scalar (l1=0): half off 0 ----------------
  ldh12(tw + 0, w_);
  {
    red4(ob + 0, xs*w_[0], xs*w_[1], xs*w_[2], xs*w_[3]);
    float xt0 = xs*t0, xt1 = xs*t1, xt2 = xs*t2;
    red4(ob + 4,  xt0*w_[4], xt1*w_[4], xt2*w_[4], xt0*w_[5]);
    red4(ob + 8,  xt1*w_[5], xt2*w_[5], xt0*w_[6], xt1*w_[6]);
    red4(ob + 12, xt2*w_[6], xt0*w_[7], xt1*w_[7], xt2*w_[7]);
    float xv0 = xs*s0, xv1 = xs*s1, xv2 = xs*s2, xv3 = xs*s3, xv4 = xs*s4;
    red4(ob + 16, xv0*w_[8],  xv1*w_[8],  xv2*w_[8],  xv3*w_[8]);
    red4(ob + 20, xv4*w_[8],  xv0*w_[9],  xv1*w_[9],  xv2*w_[9]);
    red4(ob + 24, xv3*w_[9],  xv4*w_[9],  xv0*w_[10], xv1*w_[10]);
    red4(ob + 28, xv2*w_[10], xv3*w_[10], xv4*w_[10], xv0*w_[11]);
    red4(ob + 32, xv1*w_[11], xv2*w_[11], xv3*w_[11], xv4*w_[11]);
  }

  // ---------------- vector (l1=1) ----------------
  {
    // ins1: l2=1 -> lo=0 (half off 32)
    ldh12(tw + 32, w_);
    float a0=0.f,a1=0.f,a2=0.f,a3=0.f;
    #pragma unroll
    for (int u = 0; u < 3; u++){
      float y = xp[u*3]*t0 + xp[u*3+1]*t1 + xp[u*3+2]*t2;
      a0=fmaf(y,w_[u*4+0],a0); a1=fmaf(y,w_[u*4+1],a1);
      a2=fmaf(y,w_[u*4+2],a2); a3=fmaf(y,w_[u*4+3],a3);
    }
    red4(ob + 36, a0, a1, a2, a3);
  }
  {
    // ins2: l2=1 -> lo=2 (half off 48)
    ldh12(tw + 48, w_);
    float acc[20];
    #pragma unroll
    for (int i = 0; i < 20; i++) acc[i] = 0.f;
    #pragma unroll
    for (int u = 0; u < 3; u++){
      float x0=xp[u*3], x1=xp[u*3+1], x2=xp[u*3+2];
      float y0 = CA*(x0*t2 + x2*t0);
      float y1 = CA*(x0*t1 + x1*t0);
      float y2 = CB*(2.f*x1*t1 - x0*t0 - x2*t2);
      float y3 = CA*(x1*t2 + x2*t1);
      float y4 = CA*(x2*t2 - x0*t0);
      #pragma unroll
      for (int w = 0; w < 4; w++){
        float ww = w_[u*4+w];
        acc[w*5+0]=fmaf(y0,ww,acc[w*5+0]); acc[w*5+1]=fmaf(y1,ww,acc[w*5+1]);
        acc[w*5+2]=fmaf(y2,ww,acc[w*5+2]); acc[w*5+3]=fmaf(y3,ww,acc[w*5+3]);
        acc[w*5+4]=fmaf(y4,ww,acc[w*5+4]);
      }
    }
    red4(ob + 52, acc[0],  acc[1],  acc[2],  acc[3]);
    red4(ob + 56, acc[4],  acc[5],  acc[6],  acc[7]);
    red4(ob + 60, acc[8],  acc[9],  acc[10], acc[11]);
    red4(ob + 64, acc[12], acc[13], acc[14], acc[15]);
    red4(ob + 68, acc[16], acc[17], acc[18], acc[19]);
  }
  {
    // ins0 (half off 16) + ins3 (half off 64), both -> lo=1
    float acc[12];
    #pragma unroll
    for (int i = 0; i < 12; i++) acc[i] = 0.f;
    ldh12(tw + 16, w_);
    #pragma unroll
    for (int u = 0; u < 3; u++)
      #pragma unroll
      for (int w = 0; w < 4; w++){
        float ww = w_[u*4+w];
        acc[w*3+0]=fmaf(xp[u*3+0],ww,acc[w*3+0]);
        acc[w*3+1]=fmaf(xp[u*3+1],ww,acc[w*3+1]);
        acc[w*3+2]=fmaf(xp[u*3+2],ww,acc[w*3+2]);
      }
    ldh12(tw + 64, w_);
    float N00 = -CB*s2 - CA*s4;
    float N01 =  CA*s1;
    float N02 =  CA*s0;
    float N11 =  2.f*CB*s2;
    float N12 =  CA*s3;
    float N22 = -CB*s2 + CA*s4;
    #pragma unroll
    for (int u = 0; u < 3; u++){
      float x0=xp[u*3], x1=xp[u*3+1], x2=xp[u*3+2];
      float y0 = x0*N00 + x1*N01 + x2*N02;
      float y1 = x0*N01 + x1*N11 + x2*N12;
      float y2 = x0*N02 + x1*N12 + x2*N22;
      #pragma unroll
      for (int w = 0; w < 4; w++){
        float ww = w_[u*4+w];
        acc[w*3+0]=fmaf(y0,ww,acc[w*3+0]);
        acc[w*3+1]=fmaf(y1,ww,acc[w*3+1]);
        acc[w*3+2]=fmaf(y2,ww,acc[w*3+2]);
      }
    }
    red4(ob + 40, acc[0], acc[1], acc[2],  acc[3]);
    red4(ob + 44, acc[4], acc[5], acc[6],  acc[7]);
    red4(ob + 48, acc[8], acc[9], acc[10], acc[11]);
  }

  // ---------------- tensor (l1=2) ----------------
  {
    // ins2: l2=2 -> lo=0 (half off 128)
    ldh20(tw + 128, w_);
    float a0=0.f,a1=0.f,a2=0.f,a3=0.f;
    #pragma unroll
    for (int u = 0; u < 5; u++){
      float y = xd[u*5]*s0 + xd[u*5+1]*s1 + xd[u*5+2]*s2 + xd[u*5+3]*s3 + xd[u*5+4]*s4;
      a0=fmaf(y,w_[u*4+0],a0); a1=fmaf(y,w_[u*4+1],a1);
      a2=fmaf(y,w_[u*4+2],a2); a3=fmaf(y,w_[u*4+3],a3);
    }
    red4(ob + 72, a0, a1, a2, a3);
  }
  {
    // ins1: l2=1 -> lo=1 (half off 104)
    ldh20(tw + 104, w_);
    float acc[12];
    #pragma unroll
    for (int i = 0; i < 12; i++) acc[i] = 0.f;
    #pragma unroll
    for (int u = 0; u < 5; u++){
      float x0=xd[u*5], x1=xd[u*5+1], x2=xd[u*5+2], x3=xd[u*5+3], x4=xd[u*5+4];
      float y0 = CA*(x0*t2 + x1*t1 - x4*t0) - CB*x2*t0;
      float y1 = CA*(x1*t0 + x3*t2) + 2.f*CB*x2*t1;
      float y2 = CA*(x0*t0 + x3*t1 + x4*t2) - CB*x2*t2;
      #pragma unroll
      for (int w = 0; w < 4; w++){
        float ww = w_[u*4+w];
        acc[w*3+0]=fmaf(y0,ww,acc[w*3+0]);
        acc[w*3+1]=fmaf(y1,ww,acc[w*3+1]);
        acc[w*3+2]=fmaf(y2,ww,acc[w*3+2]);
      }
    }
    red4(ob + 76, acc[0], acc[1], acc[2],  acc[3]);
    red4(ob + 80, acc[4], acc[5], acc[6],  acc[7]);
    red4(ob + 84, acc[8], acc[9], acc[10], acc[11]);
  }
  {
    // ins0 (half off 80) + ins3 (half off 152), both -> lo=2
    float acc[20];
    #pragma unroll
    for (int i = 0; i < 20; i++) acc[i] = 0.f;
    ldh20(tw + 80, w_);
    #pragma unroll
    for (int u = 0; u < 5; u++)
      #pragma unroll
      for (int w = 0; w < 4; w++){
        float ww = w_[u*4+w];
        #pragma unroll
        for (int k = 0; k < 5; k++)
          acc[w*5+k] = fmaf(xd[u*5+k], ww, acc[w*5+k]);
      }
    ldh20(tw + 152, w_);
    float h00 = 2.f*CG*s2;
    float h01 = -CH*s3;
    float h02 = 2.f*CG*s0;
    float h03 = -CH*s1;
    float h11 = -CG*s2 + CH*s4;
    float h12 = -CG*s1;
    float h13 = -CH*s0;
    float h14 =  CH*s1;
    float h22 = -2.f*CG*s2;
    float h23 = -CG*s3;
    float h24 = 2.f*CG*s4;
    float h33 = -CG*s2 - CH*s4;
    float h34 = -CH*s3;
    float h44 = 2.f*CG*s2;
    #pragma unroll
    for (int u = 0; u < 5; u++){
      float x0=xd[u*5], x1=xd[u*5+1], x2=xd[u*5+2], x3=xd[u*5+3], x4=xd[u*5+4];
      float y0 = x0*h00 + x1*h01 + x2*h02 + x3*h03;
      float y1 = x0*h01 + x1*h11 + x2*h12 + x3*h13 + x4*h14;
      float y2 = x0*h02 + x1*h12 + x2*h22 + x3*h23 + x4*h24;
      float y3 = x0*h03 + x1*h13 + x2*h23 + x3*h33 + x4*h34;
      float y4 =          x1*h14 + x2*h24 + x3*h34 + x4*h44;
      #pragma unroll
      for (int w = 0; w < 4; w++){
        float ww = w_[u*4+w];
        acc[w*5+0]=fmaf(y0,ww,acc[w*5+0]); acc[w*5+1]=fmaf(y1,ww,acc[w*5+1]);
        acc[w*5+2]=fmaf(y2,ww,acc[w*5+2]); acc[w*5+3]=fmaf(y3,ww,acc[w*5+3]);
        acc[w*5+4]=fmaf(y4,ww,acc[w*5+4]);
      }
    }
    red4(ob + 88,  acc[0],  acc[1],  acc[2],  acc[3]);
    red4(ob + 92,  acc[4],  acc[5],  acc[6],  acc[7]);
    red4(ob + 96,  acc[8],  acc[9],  acc[10], acc[11]);
    red4(ob + 100, acc[12], acc[13], acc[14], acc[15]);
    red4(ob + 104, acc[16], acc[17], acc[18], acc[19]);
  }
}

extern "C" void kernel_launch(void* const* d_in, const int* in_sizes, int n_in,
                              void* d_out, int out_size) {
  const float* f_in = (const float*)d_in[0];
  const int*   ei   = (const int*)d_in[1];
  const float* pos  = (const float*)d_in[2];
  const float* W1s  = (const float*)d_in[5];
  const float* W2s  = (const float*)d_in[6];
  const float* W1p  = (const float*)d_in[7];
  const float* W2p  = (const float*)d_in[8];
  const float* W1d  = (const float*)d_in[9];
  const float* W2d  = (const float*)d_in[10];
  float* fout = (float*)d_out;

  int E = in_sizes[1] / 2;
  int n_nodes = in_sizes[0] / 162;

  // gscale = (sqrt(2)/8 from FC) * (1/sqrt(16) neighbor norm)
  float gscale = 0.04419417382415922f;

  tab_kernel<<<NB / TBINS, 256>>>(W1s, W2s, W1p, W2p, W1d, W2d, gscale);
  nodesum_kernel<<<(n_nodes + 127) / 128, 128>>>(f_in, pos, n_nodes);
  eq_zero_kernel<<<(out_size + 255) / 256, 256>>>(fout, out_size);
  eq_edge_kernel<<<(E + TPB - 1) / TPB, TPB>>>(ei, fout, E);
}